// round 14
// baseline (speedup 1.0000x reference)
#include <cuda_runtime.h>
#include <cuda_bf16.h>
#include <cstddef>

#define NB   16
#define ND   4
#define NF   481
#define NT   500
#define CH   16
#define NH   32
#define NSEQ (NB * NF)              // 7696
#define PROB_ELEMS (NSEQ * NT)      // 3,848,000
#define H_ELEMS    (NSEQ * NH)      // 246,272

#define GPW 8
#define NGRP (NSEQ / GPW)           // 962 groups of 8 sequences

typedef unsigned long long u64;

// conv output x, layout [gw][t][g][c]  (gw = seq>>3, g = seq&7)
__device__ float g_x2[(size_t)NGRP * NT * 8 * CH];
// fallback sink for h_last
__device__ float g_hdump[H_ELEMS];

// ---------------------------------------------------------------------------
// packed f32x2 helpers
// ---------------------------------------------------------------------------
__device__ __forceinline__ u64 fma2(u64 a, u64 b, u64 c) {
    u64 d;
    asm("fma.rn.f32x2 %0, %1, %2, %3;" : "=l"(d) : "l"(a), "l"(b), "l"(c));
    return d;
}
__device__ __forceinline__ u64 add2(u64 a, u64 b) {
    u64 d;
    asm("add.rn.f32x2 %0, %1, %2;" : "=l"(d) : "l"(a), "l"(b));
    return d;
}
__device__ __forceinline__ u64 pack2(float lo, float hi) {
    u64 d;
    asm("mov.b64 %0, {%1, %2};" : "=l"(d) : "f"(lo), "f"(hi));
    return d;
}
__device__ __forceinline__ void unpack2(u64 v, float& lo, float& hi) {
    asm("mov.b64 {%0, %1}, %2;" : "=f"(lo), "=f"(hi) : "l"(v));
}
__device__ __forceinline__ float sigm(float v) {
    return __fdividef(1.f, 1.f + __expf(-v));
}
__device__ __forceinline__ float tanh_f(float v) {
    return __fdividef(2.f, 1.f + __expf(-2.f * v)) - 1.f;
}

// ---------------------------------------------------------------------------
// Kernel 1: fused conv1(K=9,pad=4)+PReLU -> conv2(K=5,pad=2)+PReLU  (f32x2)
// R6 tile (FT=32, TT=32) but 288 threads: stage B = 288 units in ONE round.
// ---------------------------------------------------------------------------
#define FT 32
#define TT 32
#define FIN 44
#define FC1 36
#define CTH 288          // conv block threads

#define W1D 576
#define W2D 1280
#define BD  32

__global__ __launch_bounds__(CTH, 2) void conv_kernel(
    const float* __restrict__ feat,
    const float* __restrict__ w1, const float* __restrict__ b1,
    const float* __restrict__ a1p,
    const float* __restrict__ w2, const float* __restrict__ b2,
    const float* __restrict__ a2p)
{
    extern __shared__ u64 smu[];
    u64* s_w1d = smu;
    u64* s_w2d = smu + W1D;
    u64* s_bd  = s_w2d + W2D;
    float* s_in = (float*)(s_bd + BD);         // [ND][FIN][TT]
    float* s_c1 = s_in + ND * FIN * TT;        // [CH][FC1][TT]

    const int tid = threadIdx.x;
    const int t0 = blockIdx.x * TT;
    const int f0 = blockIdx.y * FT;
    const int b  = blockIdx.z;
    const float a1 = a1p[0];
    const float a2 = a2p[0];

    for (int i = tid; i < W1D;  i += CTH) { float w = w1[i]; s_w1d[i] = pack2(w, w); }
    for (int i = tid; i < W2D; i += CTH)  { float w = w2[i]; s_w2d[i] = pack2(w, w); }
    if (tid < 16)       { float v = b1[tid];      s_bd[tid] = pack2(v, v); }
    else if (tid < 32)  { float v = b2[tid - 16]; s_bd[tid] = pack2(v, v); }

    for (int i = tid; i < ND * FIN * TT; i += CTH) {
        int t  = i & (TT - 1);
        int fl = (i / TT) % FIN;
        int d  = i / (TT * FIN);
        int f  = f0 - 6 + fl;
        int tg = t0 + t;
        float v = 0.f;
        if (f >= 0 && f < NF && tg < NT)
            v = feat[((b * ND + d) * NF + f) * NT + tg];
        s_in[i] = v;
    }
    __syncthreads();

    // Stage B: conv1 + PReLU.  288 units exactly: (f1i 0..35) x (tq 0..7)
    {
        int tq  = tid & 7;
        int f1i = tid >> 3;
        int f1  = f0 - 2 + f1i;
        u64 a2r[CH][2];
        if (f1 >= 0 && f1 < NF) {
            #pragma unroll
            for (int c = 0; c < CH; c++) { a2r[c][0] = s_bd[c]; a2r[c][1] = s_bd[c]; }
            #pragma unroll
            for (int d = 0; d < ND; d++)
                #pragma unroll
                for (int k = 0; k < 9; k++) {
                    const u64* vp = (const u64*)&s_in[(d * FIN + f1i + k) * TT + tq * 4];
                    u64 v0 = vp[0], v1 = vp[1];
                    #pragma unroll
                    for (int c = 0; c < CH; c++) {
                        u64 w = s_w1d[(c * ND + d) * 9 + k];
                        a2r[c][0] = fma2(w, v0, a2r[c][0]);
                        a2r[c][1] = fma2(w, v1, a2r[c][1]);
                    }
                }
            #pragma unroll
            for (int c = 0; c < CH; c++)
                #pragma unroll
                for (int hh = 0; hh < 2; hh++) {
                    float x0, x1;
                    unpack2(a2r[c][hh], x0, x1);
                    x0 = x0 >= 0.f ? x0 : a1 * x0;
                    x1 = x1 >= 0.f ? x1 : a1 * x1;
                    a2r[c][hh] = pack2(x0, x1);
                }
        } else {
            #pragma unroll
            for (int c = 0; c < CH; c++) { a2r[c][0] = 0ull; a2r[c][1] = 0ull; }
        }
        #pragma unroll
        for (int c = 0; c < CH; c++) {
            u64* op = (u64*)&s_c1[(c * FC1 + f1i) * TT + tq * 4];
            op[0] = a2r[c][0]; op[1] = a2r[c][1];
        }
    }
    __syncthreads();

    // Stage C: conv2 + PReLU + output.  256 active of 288.
    if (tid < 256) {
        int tq  = tid & 7;
        int f2i = tid >> 3;
        u64 a2r[CH][2];
        #pragma unroll
        for (int c = 0; c < CH; c++) { a2r[c][0] = s_bd[16 + c]; a2r[c][1] = s_bd[16 + c]; }
        #pragma unroll
        for (int ci = 0; ci < CH; ci++)
            #pragma unroll
            for (int k = 0; k < 5; k++) {
                const u64* vp = (const u64*)&s_c1[(ci * FC1 + f2i + k) * TT + tq * 4];
                u64 v0 = vp[0], v1 = vp[1];
                #pragma unroll
                for (int co = 0; co < CH; co++) {
                    u64 w = s_w2d[(co * CH + ci) * 5 + k];
                    a2r[co][0] = fma2(w, v0, a2r[co][0]);
                    a2r[co][1] = fma2(w, v1, a2r[co][1]);
                }
            }
        float ov[CH][4];
        #pragma unroll
        for (int c = 0; c < CH; c++) {
            unpack2(a2r[c][0], ov[c][0], ov[c][1]);
            unpack2(a2r[c][1], ov[c][2], ov[c][3]);
            #pragma unroll
            for (int tw = 0; tw < 4; tw++) {
                float x = ov[c][tw];
                ov[c][tw] = x >= 0.f ? x : a2 * x;
            }
        }
        int f = f0 + f2i;
        if (f < NF) {
            int seq = b * NF + f;
            size_t base = (size_t)(seq >> 3) * NT * 128 + (seq & 7) * 16;
            #pragma unroll
            for (int tw = 0; tw < 4; tw++) {
                int t = t0 + tq * 4 + tw;
                if (t < NT) {
                    float* o = g_x2 + base + (size_t)t * 128;
                    #pragma unroll
                    for (int c4 = 0; c4 < 4; c4++)
                        *(float4*)(o + c4 * 4) = make_float4(
                            ov[c4 * 4 + 0][tw], ov[c4 * 4 + 1][tw],
                            ov[c4 * 4 + 2][tw], ov[c4 * 4 + 3][tw]);
                }
            }
        }
    }
}

// ---------------------------------------------------------------------------
// Kernel 2: persistent GRU.  962 x 1-warp blocks.  EXACT R12 version
// (R10 loop + fc software-pipelined by one step): measured 1073us.
// ---------------------------------------------------------------------------
__global__ __launch_bounds__(32) void gru_kernel(
    const float* __restrict__ h0,
    const float* __restrict__ w_ih, const float* __restrict__ w_hh,
    const float* __restrict__ b_ih, const float* __restrict__ b_hh,
    const float* __restrict__ fc_w, const float* __restrict__ fc_b,
    float* __restrict__ prob, float* __restrict__ hlast)
{
    __shared__ float4 s_whhA[NH][NH];     // [k][j] = (wr,wr,wz,wz)   16KB
    __shared__ u64   s_fcw[NH];           // (fcw,fcw) per k          256B
    __shared__ u64   s_hh[NH][4];         // [k][pair]                1KB
    __shared__ float s_xT[CH][12];        // [c][g] padded            768B

    const int lane = threadIdx.x;
    const int j = lane;

    for (int k = 0; k < NH; k++) {
        float wr = w_hh[j * NH + k];
        float wz = w_hh[(NH + j) * NH + k];
        s_whhA[k][j] = make_float4(wr, wr, wz, wz);
    }
    { float w = fc_w[lane]; s_fcw[lane] = pack2(w, w); }

    const int gw = blockIdx.x;
    const int sbase = gw * GPW;

    u64 wxr[CH], wxz[CH], wxn[CH], whn[NH];
    #pragma unroll
    for (int c = 0; c < CH; c++) {
        float wr = w_ih[j * CH + c];
        float wz = w_ih[(NH + j) * CH + c];
        float wn = w_ih[(2 * NH + j) * CH + c];
        wxr[c] = pack2(wr, wr); wxz[c] = pack2(wz, wz); wxn[c] = pack2(wn, wn);
    }
    #pragma unroll
    for (int k = 0; k < NH; k++) {
        float wn = w_hh[(2 * NH + j) * NH + k];
        whn[k] = pack2(wn, wn);
    }

    const float brf  = b_ih[j] + b_hh[j];
    const float bzf  = b_ih[NH + j] + b_hh[NH + j];
    const float bxnf = b_ih[2 * NH + j];
    const float bhnf = b_hh[2 * NH + j];
    const u64 br2  = pack2(brf, brf);
    const u64 bz2  = pack2(bzf, bzf);
    const u64 bxn2 = pack2(bxnf, bxnf);
    const u64 bhn2 = pack2(bhnf, bhnf);
    const float fcb = fc_b[0];

    float hreg[GPW];
    #pragma unroll
    for (int g = 0; g < GPW; g++) hreg[g] = h0[(sbase + g) * NH + j];
    {
        ulonglong2 v0, v1;
        v0.x = pack2(hreg[0], hreg[1]); v0.y = pack2(hreg[2], hreg[3]);
        v1.x = pack2(hreg[4], hreg[5]); v1.y = pack2(hreg[6], hreg[7]);
        *(ulonglong2*)&s_hh[j][0] = v0;
        *(ulonglong2*)&s_hh[j][2] = v1;
    }

    const int lg = lane >> 2, lc4 = lane & 3;
    const int p = lane & 3;     // fc pair handled (redundantly) by this lane
    const float* xptr = g_x2 + (size_t)gw * NT * 128 + lg * 16 + lc4 * 4;
    float4 xv = *(const float4*)xptr;
    float* sx = &s_xT[0][0];
    __syncwarp();

    for (int t = 0; t < NT; t++) {
        sx[(lc4 * 4 + 0) * 12 + lg] = xv.x;
        sx[(lc4 * 4 + 1) * 12 + lg] = xv.y;
        sx[(lc4 * 4 + 2) * 12 + lg] = xv.z;
        sx[(lc4 * 4 + 3) * 12 + lg] = xv.w;
        __syncwarp();   // publishes x(t) AND the s_hh store from step t-1
        if (t + 1 < NT)
            xv = *(const float4*)(xptr + (size_t)(t + 1) * 128);

        // deferred fc for step t-1 (s_hh holds h_{t-1}); overlaps accumulation
        if (t > 0) {
            u64 f0a = 0ull, f1a = 0ull, f2a = 0ull, f3a = 0ull;
            #pragma unroll
            for (int k8 = 0; k8 < 8; k8++) {
                f0a = fma2(s_fcw[k8],      s_hh[k8][p],      f0a);
                f1a = fma2(s_fcw[8 + k8],  s_hh[8 + k8][p],  f1a);
                f2a = fma2(s_fcw[16 + k8], s_hh[16 + k8][p], f2a);
                f3a = fma2(s_fcw[24 + k8], s_hh[24 + k8][p], f3a);
            }
            u64 facc = add2(add2(f0a, f1a), add2(f2a, f3a));
            float f0v, f1v;
            unpack2(facc, f0v, f1v);
            if (lane < 4) {
                prob[(size_t)(sbase + 2 * p) * NT + (t - 1)]     = sigm(f0v + fcb);
                prob[(size_t)(sbase + 2 * p + 1) * NT + (t - 1)] = sigm(f1v + fcb);
            }
        }

        u64 ar[4], az[4], axn[4], ahn[4];
        #pragma unroll
        for (int q = 0; q < 4; q++) { ar[q] = br2; az[q] = bz2; axn[q] = bxn2; ahn[q] = bhn2; }

        // h @ w_hh^T
        #pragma unroll
        for (int k = 0; k < NH; k++) {
            ulonglong2 wA = *(const ulonglong2*)&s_whhA[k][j];
            ulonglong2 hA = *(const ulonglong2*)&s_hh[k][0];
            ulonglong2 hB = *(const ulonglong2*)&s_hh[k][2];
            ar[0]  = fma2(wA.x,   hA.x, ar[0]);  ar[1]  = fma2(wA.x,   hA.y, ar[1]);
            ar[2]  = fma2(wA.x,   hB.x, ar[2]);  ar[3]  = fma2(wA.x,   hB.y, ar[3]);
            az[0]  = fma2(wA.y,   hA.x, az[0]);  az[1]  = fma2(wA.y,   hA.y, az[1]);
            az[2]  = fma2(wA.y,   hB.x, az[2]);  az[3]  = fma2(wA.y,   hB.y, az[3]);
            ahn[0] = fma2(whn[k], hA.x, ahn[0]); ahn[1] = fma2(whn[k], hA.y, ahn[1]);
            ahn[2] = fma2(whn[k], hB.x, ahn[2]); ahn[3] = fma2(whn[k], hB.y, ahn[3]);
        }
        // x @ w_ih^T
        #pragma unroll
        for (int c = 0; c < CH; c++) {
            const float* r = &s_xT[c][0];
            ulonglong2 xA = *(const ulonglong2*)r;
            ulonglong2 xB = *(const ulonglong2*)(r + 4);
            ar[0]  = fma2(wxr[c], xA.x, ar[0]);  ar[1]  = fma2(wxr[c], xA.y, ar[1]);
            ar[2]  = fma2(wxr[c], xB.x, ar[2]);  ar[3]  = fma2(wxr[c], xB.y, ar[3]);
            az[0]  = fma2(wxz[c], xA.x, az[0]);  az[1]  = fma2(wxz[c], xA.y, az[1]);
            az[2]  = fma2(wxz[c], xB.x, az[2]);  az[3]  = fma2(wxz[c], xB.y, az[3]);
            axn[0] = fma2(wxn[c], xA.x, axn[0]); axn[1] = fma2(wxn[c], xA.y, axn[1]);
            axn[2] = fma2(wxn[c], xB.x, axn[2]); axn[3] = fma2(wxn[c], xB.y, axn[3]);
        }

        float hnew[GPW];
        #pragma unroll
        for (int q = 0; q < 4; q++) {
            float arv0, arv1, azv0, azv1, xn0, xn1, hn0, hn1;
            unpack2(ar[q],  arv0, arv1);
            unpack2(az[q],  azv0, azv1);
            unpack2(axn[q], xn0,  xn1);
            unpack2(ahn[q], hn0,  hn1);
            float r0 = sigm(arv0), r1 = sigm(arv1);
            float z0 = sigm(azv0), z1 = sigm(azv1);
            float n0 = tanh_f(fmaf(r0, hn0, xn0));
            float n1 = tanh_f(fmaf(r1, hn1, xn1));
            hnew[2 * q]     = fmaf(z0, hreg[2 * q]     - n0, n0);
            hnew[2 * q + 1] = fmaf(z1, hreg[2 * q + 1] - n1, n1);
        }

        __syncwarp();   // all lanes' s_hh reads (fc + hh-loop) done
        {
            ulonglong2 v0, v1;
            v0.x = pack2(hnew[0], hnew[1]); v0.y = pack2(hnew[2], hnew[3]);
            v1.x = pack2(hnew[4], hnew[5]); v1.y = pack2(hnew[6], hnew[7]);
            *(ulonglong2*)&s_hh[j][0] = v0;
            *(ulonglong2*)&s_hh[j][2] = v1;
        }
        #pragma unroll
        for (int g = 0; g < GPW; g++) hreg[g] = hnew[g];
    }
    __syncwarp();   // final s_hh store visible

    // epilogue fc for t = NT-1
    {
        u64 f0a = 0ull, f1a = 0ull, f2a = 0ull, f3a = 0ull;
        #pragma unroll
        for (int k8 = 0; k8 < 8; k8++) {
            f0a = fma2(s_fcw[k8],      s_hh[k8][p],      f0a);
            f1a = fma2(s_fcw[8 + k8],  s_hh[8 + k8][p],  f1a);
            f2a = fma2(s_fcw[16 + k8], s_hh[16 + k8][p], f2a);
            f3a = fma2(s_fcw[24 + k8], s_hh[24 + k8][p], f3a);
        }
        u64 facc = add2(add2(f0a, f1a), add2(f2a, f3a));
        float f0v, f1v;
        unpack2(facc, f0v, f1v);
        if (lane < 4) {
            prob[(size_t)(sbase + 2 * p) * NT + (NT - 1)]     = sigm(f0v + fcb);
            prob[(size_t)(sbase + 2 * p + 1) * NT + (NT - 1)] = sigm(f1v + fcb);
        }
    }

    #pragma unroll
    for (int g = 0; g < GPW; g++)
        hlast[(sbase + g) * NH + j] = hreg[g];
}

// ---------------------------------------------------------------------------
extern "C" void kernel_launch(void* const* d_in, const int* in_sizes, int n_in,
                              void* d_out, int out_size)
{
    const float* feat  = (const float*)d_in[0];
    const float* h0    = (const float*)d_in[1];
    const float* w1    = (const float*)d_in[2];
    const float* b1    = (const float*)d_in[3];
    const float* a1    = (const float*)d_in[4];
    const float* w2    = (const float*)d_in[5];
    const float* b2    = (const float*)d_in[6];
    const float* a2    = (const float*)d_in[7];
    const float* w_ih  = (const float*)d_in[8];
    const float* w_hh  = (const float*)d_in[9];
    const float* b_ih  = (const float*)d_in[10];
    const float* b_hh  = (const float*)d_in[11];
    const float* fc_w  = (const float*)d_in[12];
    const float* fc_b  = (const float*)d_in[13];

    float* prob = (float*)d_out;
    float* hlast;
    if (out_size >= PROB_ELEMS + H_ELEMS) {
        hlast = prob + PROB_ELEMS;
    } else {
        void* p = nullptr;
        cudaGetSymbolAddress(&p, g_hdump);
        hlast = (float*)p;
    }

    const int smem_bytes = (W1D + W2D + BD) * 8 + (ND * FIN * TT + CH * FC1 * TT) * 4;
    cudaFuncSetAttribute(conv_kernel, cudaFuncAttributeMaxDynamicSharedMemorySize,
                         smem_bytes);

    dim3 cgrid((NT + TT - 1) / TT, (NF + FT - 1) / FT, NB);   // 16,16,16
    conv_kernel<<<cgrid, CTH, smem_bytes>>>(feat, w1, b1, a1, w2, b2, a2);

    gru_kernel<<<NGRP, 32>>>(h0, w_ih, w_hh, b_ih, b_hh, fc_w, fc_b,
                             prob, hlast);
}

// round 15
// speedup vs baseline: 1.6662x; 1.6662x over previous
#include <cuda_runtime.h>
#include <cuda_bf16.h>
#include <cstddef>

#define NB   16
#define ND   4
#define NF   481
#define NT   500
#define CH   16
#define NH   32
#define NSEQ (NB * NF)              // 7696
#define PROB_ELEMS (NSEQ * NT)      // 3,848,000
#define H_ELEMS    (NSEQ * NH)      // 246,272

#define GPW 8
#define NGRP (NSEQ / GPW)           // 962 groups of 8 sequences

typedef unsigned long long u64;

// conv output x, layout [gw][t][g][c]  (gw = seq>>3, g = seq&7)
__device__ float g_x2[(size_t)NGRP * NT * 8 * CH];
// fallback sink for h_last
__device__ float g_hdump[H_ELEMS];

// ---------------------------------------------------------------------------
// packed f32x2 helpers
// ---------------------------------------------------------------------------
__device__ __forceinline__ u64 fma2(u64 a, u64 b, u64 c) {
    u64 d;
    asm("fma.rn.f32x2 %0, %1, %2, %3;" : "=l"(d) : "l"(a), "l"(b), "l"(c));
    return d;
}
__device__ __forceinline__ u64 add2(u64 a, u64 b) {
    u64 d;
    asm("add.rn.f32x2 %0, %1, %2;" : "=l"(d) : "l"(a), "l"(b));
    return d;
}
__device__ __forceinline__ u64 pack2(float lo, float hi) {
    u64 d;
    asm("mov.b64 %0, {%1, %2};" : "=l"(d) : "f"(lo), "f"(hi));
    return d;
}
__device__ __forceinline__ void unpack2(u64 v, float& lo, float& hi) {
    asm("mov.b64 {%0, %1}, %2;" : "=f"(lo), "=f"(hi) : "l"(v));
}
__device__ __forceinline__ float sigm(float v) {
    return __fdividef(1.f, 1.f + __expf(-v));
}
__device__ __forceinline__ float tanh_f(float v) {
    return __fdividef(2.f, 1.f + __expf(-2.f * v)) - 1.f;
}

// ---------------------------------------------------------------------------
// Kernel 1: fused conv1(K=9,pad=4)+PReLU -> conv2(K=5,pad=2)+PReLU  (f32x2)
// Champion config (R6): FT=32, TT=32, 256 threads, launch_bounds(256,2).
// ---------------------------------------------------------------------------
#define FT 32
#define TT 32
#define FIN 44
#define FC1 36

#define W1D 576
#define W2D 1280
#define BD  32

__global__ __launch_bounds__(256, 2) void conv_kernel(
    const float* __restrict__ feat,
    const float* __restrict__ w1, const float* __restrict__ b1,
    const float* __restrict__ a1p,
    const float* __restrict__ w2, const float* __restrict__ b2,
    const float* __restrict__ a2p)
{
    extern __shared__ u64 smu[];
    u64* s_w1d = smu;
    u64* s_w2d = smu + W1D;
    u64* s_bd  = s_w2d + W2D;
    float* s_in = (float*)(s_bd + BD);
    float* s_c1 = s_in + ND * FIN * TT;

    const int tid = threadIdx.x;
    const int t0 = blockIdx.x * TT;
    const int f0 = blockIdx.y * FT;
    const int b  = blockIdx.z;
    const float a1 = a1p[0];
    const float a2 = a2p[0];

    for (int i = tid; i < W1D;  i += 256) { float w = w1[i]; s_w1d[i] = pack2(w, w); }
    for (int i = tid; i < W2D; i += 256)  { float w = w2[i]; s_w2d[i] = pack2(w, w); }
    if (tid < 16)       { float v = b1[tid];      s_bd[tid] = pack2(v, v); }
    else if (tid < 32)  { float v = b2[tid - 16]; s_bd[tid] = pack2(v, v); }

    for (int i = tid; i < ND * FIN * TT; i += 256) {
        int t  = i & (TT - 1);
        int fl = (i / TT) % FIN;
        int d  = i / (TT * FIN);
        int f  = f0 - 6 + fl;
        int tg = t0 + t;
        float v = 0.f;
        if (f >= 0 && f < NF && tg < NT)
            v = feat[((b * ND + d) * NF + f) * NT + tg];
        s_in[i] = v;
    }
    __syncthreads();

    // Stage B: conv1 + PReLU
    for (int u = tid; u < FC1 * 8; u += 256) {
        int tq  = u & 7;
        int f1i = u >> 3;
        int f1  = f0 - 2 + f1i;
        u64 a2r[CH][2];
        if (f1 >= 0 && f1 < NF) {
            #pragma unroll
            for (int c = 0; c < CH; c++) { a2r[c][0] = s_bd[c]; a2r[c][1] = s_bd[c]; }
            #pragma unroll
            for (int d = 0; d < ND; d++)
                #pragma unroll
                for (int k = 0; k < 9; k++) {
                    const u64* vp = (const u64*)&s_in[(d * FIN + f1i + k) * TT + tq * 4];
                    u64 v0 = vp[0], v1 = vp[1];
                    #pragma unroll
                    for (int c = 0; c < CH; c++) {
                        u64 w = s_w1d[(c * ND + d) * 9 + k];
                        a2r[c][0] = fma2(w, v0, a2r[c][0]);
                        a2r[c][1] = fma2(w, v1, a2r[c][1]);
                    }
                }
            #pragma unroll
            for (int c = 0; c < CH; c++)
                #pragma unroll
                for (int hh = 0; hh < 2; hh++) {
                    float x0, x1;
                    unpack2(a2r[c][hh], x0, x1);
                    x0 = x0 >= 0.f ? x0 : a1 * x0;
                    x1 = x1 >= 0.f ? x1 : a1 * x1;
                    a2r[c][hh] = pack2(x0, x1);
                }
        } else {
            #pragma unroll
            for (int c = 0; c < CH; c++) { a2r[c][0] = 0ull; a2r[c][1] = 0ull; }
        }
        #pragma unroll
        for (int c = 0; c < CH; c++) {
            u64* op = (u64*)&s_c1[(c * FC1 + f1i) * TT + tq * 4];
            op[0] = a2r[c][0]; op[1] = a2r[c][1];
        }
    }
    __syncthreads();

    // Stage C: conv2 + PReLU + layout-converted output
    {
        int tq  = tid & 7;
        int f2i = tid >> 3;
        u64 a2r[CH][2];
        #pragma unroll
        for (int c = 0; c < CH; c++) { a2r[c][0] = s_bd[16 + c]; a2r[c][1] = s_bd[16 + c]; }
        #pragma unroll
        for (int ci = 0; ci < CH; ci++)
            #pragma unroll
            for (int k = 0; k < 5; k++) {
                const u64* vp = (const u64*)&s_c1[(ci * FC1 + f2i + k) * TT + tq * 4];
                u64 v0 = vp[0], v1 = vp[1];
                #pragma unroll
                for (int co = 0; co < CH; co++) {
                    u64 w = s_w2d[(co * CH + ci) * 5 + k];
                    a2r[co][0] = fma2(w, v0, a2r[co][0]);
                    a2r[co][1] = fma2(w, v1, a2r[co][1]);
                }
            }
        float ov[CH][4];
        #pragma unroll
        for (int c = 0; c < CH; c++) {
            unpack2(a2r[c][0], ov[c][0], ov[c][1]);
            unpack2(a2r[c][1], ov[c][2], ov[c][3]);
            #pragma unroll
            for (int tw = 0; tw < 4; tw++) {
                float x = ov[c][tw];
                ov[c][tw] = x >= 0.f ? x : a2 * x;
            }
        }
        int f = f0 + f2i;
        if (f < NF) {
            int seq = b * NF + f;
            size_t base = (size_t)(seq >> 3) * NT * 128 + (seq & 7) * 16;
            #pragma unroll
            for (int tw = 0; tw < 4; tw++) {
                int t = t0 + tq * 4 + tw;
                if (t < NT) {
                    float* o = g_x2 + base + (size_t)t * 128;
                    #pragma unroll
                    for (int c4 = 0; c4 < 4; c4++)
                        *(float4*)(o + c4 * 4) = make_float4(
                            ov[c4 * 4 + 0][tw], ov[c4 * 4 + 1][tw],
                            ov[c4 * 4 + 2][tw], ov[c4 * 4 + 3][tw]);
                }
            }
        }
    }
}

// ---------------------------------------------------------------------------
// Kernel 2: persistent GRU.  962 x 1-warp blocks.  Best-measured version
// (R12): R6 loop + fc software-pipelined by one step.  1073us.
// ---------------------------------------------------------------------------
__global__ __launch_bounds__(32) void gru_kernel(
    const float* __restrict__ h0,
    const float* __restrict__ w_ih, const float* __restrict__ w_hh,
    const float* __restrict__ b_ih, const float* __restrict__ b_hh,
    const float* __restrict__ fc_w, const float* __restrict__ fc_b,
    float* __restrict__ prob, float* __restrict__ hlast)
{
    __shared__ float4 s_whhA[NH][NH];     // [k][j] = (wr,wr,wz,wz)   16KB
    __shared__ u64   s_fcw[NH];           // (fcw,fcw) per k          256B
    __shared__ u64   s_hh[NH][4];         // [k][pair]                1KB
    __shared__ float s_xT[CH][12];        // [c][g] padded            768B

    const int lane = threadIdx.x;
    const int j = lane;

    for (int k = 0; k < NH; k++) {
        float wr = w_hh[j * NH + k];
        float wz = w_hh[(NH + j) * NH + k];
        s_whhA[k][j] = make_float4(wr, wr, wz, wz);
    }
    { float w = fc_w[lane]; s_fcw[lane] = pack2(w, w); }

    const int gw = blockIdx.x;
    const int sbase = gw * GPW;

    u64 wxr[CH], wxz[CH], wxn[CH], whn[NH];
    #pragma unroll
    for (int c = 0; c < CH; c++) {
        float wr = w_ih[j * CH + c];
        float wz = w_ih[(NH + j) * CH + c];
        float wn = w_ih[(2 * NH + j) * CH + c];
        wxr[c] = pack2(wr, wr); wxz[c] = pack2(wz, wz); wxn[c] = pack2(wn, wn);
    }
    #pragma unroll
    for (int k = 0; k < NH; k++) {
        float wn = w_hh[(2 * NH + j) * NH + k];
        whn[k] = pack2(wn, wn);
    }

    const float brf  = b_ih[j] + b_hh[j];
    const float bzf  = b_ih[NH + j] + b_hh[NH + j];
    const float bxnf = b_ih[2 * NH + j];
    const float bhnf = b_hh[2 * NH + j];
    const u64 br2  = pack2(brf, brf);
    const u64 bz2  = pack2(bzf, bzf);
    const u64 bxn2 = pack2(bxnf, bxnf);
    const u64 bhn2 = pack2(bhnf, bhnf);
    const float fcb = fc_b[0];

    float hreg[GPW];
    #pragma unroll
    for (int g = 0; g < GPW; g++) hreg[g] = h0[(sbase + g) * NH + j];
    {
        ulonglong2 v0, v1;
        v0.x = pack2(hreg[0], hreg[1]); v0.y = pack2(hreg[2], hreg[3]);
        v1.x = pack2(hreg[4], hreg[5]); v1.y = pack2(hreg[6], hreg[7]);
        *(ulonglong2*)&s_hh[j][0] = v0;
        *(ulonglong2*)&s_hh[j][2] = v1;
    }

    const int lg = lane >> 2, lc4 = lane & 3;
    const int p = lane & 3;     // fc pair handled (redundantly) by this lane
    const float* xptr = g_x2 + (size_t)gw * NT * 128 + lg * 16 + lc4 * 4;
    float4 xv = *(const float4*)xptr;
    float* sx = &s_xT[0][0];
    __syncwarp();

    for (int t = 0; t < NT; t++) {
        sx[(lc4 * 4 + 0) * 12 + lg] = xv.x;
        sx[(lc4 * 4 + 1) * 12 + lg] = xv.y;
        sx[(lc4 * 4 + 2) * 12 + lg] = xv.z;
        sx[(lc4 * 4 + 3) * 12 + lg] = xv.w;
        __syncwarp();   // publishes x(t) AND the s_hh store from step t-1
        if (t + 1 < NT)
            xv = *(const float4*)(xptr + (size_t)(t + 1) * 128);

        // deferred fc for step t-1 (s_hh holds h_{t-1}); overlaps accumulation
        if (t > 0) {
            u64 f0a = 0ull, f1a = 0ull, f2a = 0ull, f3a = 0ull;
            #pragma unroll
            for (int k8 = 0; k8 < 8; k8++) {
                f0a = fma2(s_fcw[k8],      s_hh[k8][p],      f0a);
                f1a = fma2(s_fcw[8 + k8],  s_hh[8 + k8][p],  f1a);
                f2a = fma2(s_fcw[16 + k8], s_hh[16 + k8][p], f2a);
                f3a = fma2(s_fcw[24 + k8], s_hh[24 + k8][p], f3a);
            }
            u64 facc = add2(add2(f0a, f1a), add2(f2a, f3a));
            float f0v, f1v;
            unpack2(facc, f0v, f1v);
            if (lane < 4) {
                prob[(size_t)(sbase + 2 * p) * NT + (t - 1)]     = sigm(f0v + fcb);
                prob[(size_t)(sbase + 2 * p + 1) * NT + (t - 1)] = sigm(f1v + fcb);
            }
        }

        u64 ar[4], az[4], axn[4], ahn[4];
        #pragma unroll
        for (int q = 0; q < 4; q++) { ar[q] = br2; az[q] = bz2; axn[q] = bxn2; ahn[q] = bhn2; }

        // h @ w_hh^T
        #pragma unroll
        for (int k = 0; k < NH; k++) {
            ulonglong2 wA = *(const ulonglong2*)&s_whhA[k][j];
            ulonglong2 hA = *(const ulonglong2*)&s_hh[k][0];
            ulonglong2 hB = *(const ulonglong2*)&s_hh[k][2];
            ar[0]  = fma2(wA.x,   hA.x, ar[0]);  ar[1]  = fma2(wA.x,   hA.y, ar[1]);
            ar[2]  = fma2(wA.x,   hB.x, ar[2]);  ar[3]  = fma2(wA.x,   hB.y, ar[3]);
            az[0]  = fma2(wA.y,   hA.x, az[0]);  az[1]  = fma2(wA.y,   hA.y, az[1]);
            az[2]  = fma2(wA.y,   hB.x, az[2]);  az[3]  = fma2(wA.y,   hB.y, az[3]);
            ahn[0] = fma2(whn[k], hA.x, ahn[0]); ahn[1] = fma2(whn[k], hA.y, ahn[1]);
            ahn[2] = fma2(whn[k], hB.x, ahn[2]); ahn[3] = fma2(whn[k], hB.y, ahn[3]);
        }
        // x @ w_ih^T
        #pragma unroll
        for (int c = 0; c < CH; c++) {
            const float* r = &s_xT[c][0];
            ulonglong2 xA = *(const ulonglong2*)r;
            ulonglong2 xB = *(const ulonglong2*)(r + 4);
            ar[0]  = fma2(wxr[c], xA.x, ar[0]);  ar[1]  = fma2(wxr[c], xA.y, ar[1]);
            ar[2]  = fma2(wxr[c], xB.x, ar[2]);  ar[3]  = fma2(wxr[c], xB.y, ar[3]);
            az[0]  = fma2(wxz[c], xA.x, az[0]);  az[1]  = fma2(wxz[c], xA.y, az[1]);
            az[2]  = fma2(wxz[c], xB.x, az[2]);  az[3]  = fma2(wxz[c], xB.y, az[3]);
            axn[0] = fma2(wxn[c], xA.x, axn[0]); axn[1] = fma2(wxn[c], xA.y, axn[1]);
            axn[2] = fma2(wxn[c], xB.x, axn[2]); axn[3] = fma2(wxn[c], xB.y, axn[3]);
        }

        float hnew[GPW];
        #pragma unroll
        for (int q = 0; q < 4; q++) {
            float arv0, arv1, azv0, azv1, xn0, xn1, hn0, hn1;
            unpack2(ar[q],  arv0, arv1);
            unpack2(az[q],  azv0, azv1);
            unpack2(axn[q], xn0,  xn1);
            unpack2(ahn[q], hn0,  hn1);
            float r0 = sigm(arv0), r1 = sigm(arv1);
            float z0 = sigm(azv0), z1 = sigm(azv1);
            float n0 = tanh_f(fmaf(r0, hn0, xn0));
            float n1 = tanh_f(fmaf(r1, hn1, xn1));
            hnew[2 * q]     = fmaf(z0, hreg[2 * q]     - n0, n0);
            hnew[2 * q + 1] = fmaf(z1, hreg[2 * q + 1] - n1, n1);
        }

        __syncwarp();   // all lanes' s_hh reads (fc + hh-loop) done
        {
            ulonglong2 v0, v1;
            v0.x = pack2(hnew[0], hnew[1]); v0.y = pack2(hnew[2], hnew[3]);
            v1.x = pack2(hnew[4], hnew[5]); v1.y = pack2(hnew[6], hnew[7]);
            *(ulonglong2*)&s_hh[j][0] = v0;
            *(ulonglong2*)&s_hh[j][2] = v1;
        }
        #pragma unroll
        for (int g = 0; g < GPW; g++) hreg[g] = hnew[g];
    }
    __syncwarp();   // final s_hh store visible

    // epilogue fc for t = NT-1
    {
        u64 f0a = 0ull, f1a = 0ull, f2a = 0ull, f3a = 0ull;
        #pragma unroll
        for (int k8 = 0; k8 < 8; k8++) {
            f0a = fma2(s_fcw[k8],      s_hh[k8][p],      f0a);
            f1a = fma2(s_fcw[8 + k8],  s_hh[8 + k8][p],  f1a);
            f2a = fma2(s_fcw[16 + k8], s_hh[16 + k8][p], f2a);
            f3a = fma2(s_fcw[24 + k8], s_hh[24 + k8][p], f3a);
        }
        u64 facc = add2(add2(f0a, f1a), add2(f2a, f3a));
        float f0v, f1v;
        unpack2(facc, f0v, f1v);
        if (lane < 4) {
            prob[(size_t)(sbase + 2 * p) * NT + (NT - 1)]     = sigm(f0v + fcb);
            prob[(size_t)(sbase + 2 * p + 1) * NT + (NT - 1)] = sigm(f1v + fcb);
        }
    }

    #pragma unroll
    for (int g = 0; g < GPW; g++)
        hlast[(sbase + g) * NH + j] = hreg[g];
}

// ---------------------------------------------------------------------------
extern "C" void kernel_launch(void* const* d_in, const int* in_sizes, int n_in,
                              void* d_out, int out_size)
{
    const float* feat  = (const float*)d_in[0];
    const float* h0    = (const float*)d_in[1];
    const float* w1    = (const float*)d_in[2];
    const float* b1    = (const float*)d_in[3];
    const float* a1    = (const float*)d_in[4];
    const float* w2    = (const float*)d_in[5];
    const float* b2    = (const float*)d_in[6];
    const float* a2    = (const float*)d_in[7];
    const float* w_ih  = (const float*)d_in[8];
    const float* w_hh  = (const float*)d_in[9];
    const float* b_ih  = (const float*)d_in[10];
    const float* b_hh  = (const float*)d_in[11];
    const float* fc_w  = (const float*)d_in[12];
    const float* fc_b  = (const float*)d_in[13];

    float* prob = (float*)d_out;
    float* hlast;
    if (out_size >= PROB_ELEMS + H_ELEMS) {
        hlast = prob + PROB_ELEMS;
    } else {
        void* p = nullptr;
        cudaGetSymbolAddress(&p, g_hdump);
        hlast = (float*)p;
    }

    const int smem_bytes = (W1D + W2D + BD) * 8 + (ND * FIN * TT + CH * FC1 * TT) * 4;
    cudaFuncSetAttribute(conv_kernel, cudaFuncAttributeMaxDynamicSharedMemorySize,
                         smem_bytes);

    dim3 cgrid((NT + TT - 1) / TT, (NF + FT - 1) / FT, NB);   // 16,16,16
    conv_kernel<<<cgrid, 256, smem_bytes>>>(feat, w1, b1, a1, w2, b2, a2);

    gru_kernel<<<NGRP, 32>>>(h0, w_ih, w_hh, b_ih, b_hh, fc_w, fc_b,
                             prob, hlast);
}

// round 16
// speedup vs baseline: 1.6701x; 1.0023x over previous
#include <cuda_runtime.h>
#include <cuda_bf16.h>
#include <cstddef>

#define NB   16
#define ND   4
#define NF   481
#define NT   500
#define CH   16
#define NH   32
#define NSEQ (NB * NF)              // 7696
#define PROB_ELEMS (NSEQ * NT)      // 3,848,000
#define H_ELEMS    (NSEQ * NH)      // 246,272

#define GPW 8
#define NGRP (NSEQ / GPW)           // 962 groups of 8 sequences

typedef unsigned long long u64;

// conv output x, layout [gw][t][g][c]  (gw = seq>>3, g = seq&7)
__device__ float g_x2[(size_t)NGRP * NT * 8 * CH];
// fallback sink for h_last
__device__ float g_hdump[H_ELEMS];

// ---------------------------------------------------------------------------
// packed f32x2 helpers
// ---------------------------------------------------------------------------
__device__ __forceinline__ u64 fma2(u64 a, u64 b, u64 c) {
    u64 d;
    asm("fma.rn.f32x2 %0, %1, %2, %3;" : "=l"(d) : "l"(a), "l"(b), "l"(c));
    return d;
}
__device__ __forceinline__ u64 add2(u64 a, u64 b) {
    u64 d;
    asm("add.rn.f32x2 %0, %1, %2;" : "=l"(d) : "l"(a), "l"(b));
    return d;
}
__device__ __forceinline__ u64 pack2(float lo, float hi) {
    u64 d;
    asm("mov.b64 %0, {%1, %2};" : "=l"(d) : "f"(lo), "f"(hi));
    return d;
}
__device__ __forceinline__ void unpack2(u64 v, float& lo, float& hi) {
    asm("mov.b64 {%0, %1}, %2;" : "=f"(lo), "=f"(hi) : "l"(v));
}
__device__ __forceinline__ float sigm(float v) {
    return __fdividef(1.f, 1.f + __expf(-v));
}
__device__ __forceinline__ float tanh_f(float v) {
    return __fdividef(2.f, 1.f + __expf(-2.f * v)) - 1.f;
}

// ---------------------------------------------------------------------------
// Kernel 1: fused conv1(K=9,pad=4)+PReLU -> conv2(K=5,pad=2)+PReLU  (f32x2)
// Champion config: FT=32, TT=32, 256 threads, launch_bounds(256,2), 128 regs.
// ---------------------------------------------------------------------------
#define FT 32
#define TT 32
#define FIN 44
#define FC1 36

#define W1D 576
#define W2D 1280
#define BD  32

__global__ __launch_bounds__(256, 2) void conv_kernel(
    const float* __restrict__ feat,
    const float* __restrict__ w1, const float* __restrict__ b1,
    const float* __restrict__ a1p,
    const float* __restrict__ w2, const float* __restrict__ b2,
    const float* __restrict__ a2p)
{
    extern __shared__ u64 smu[];
    u64* s_w1d = smu;
    u64* s_w2d = smu + W1D;
    u64* s_bd  = s_w2d + W2D;
    float* s_in = (float*)(s_bd + BD);
    float* s_c1 = s_in + ND * FIN * TT;

    const int tid = threadIdx.x;
    const int t0 = blockIdx.x * TT;
    const int f0 = blockIdx.y * FT;
    const int b  = blockIdx.z;
    const float a1 = a1p[0];
    const float a2 = a2p[0];

    for (int i = tid; i < W1D;  i += 256) { float w = w1[i]; s_w1d[i] = pack2(w, w); }
    for (int i = tid; i < W2D; i += 256)  { float w = w2[i]; s_w2d[i] = pack2(w, w); }
    if (tid < 16)       { float v = b1[tid];      s_bd[tid] = pack2(v, v); }
    else if (tid < 32)  { float v = b2[tid - 16]; s_bd[tid] = pack2(v, v); }

    for (int i = tid; i < ND * FIN * TT; i += 256) {
        int t  = i & (TT - 1);
        int fl = (i / TT) % FIN;
        int d  = i / (TT * FIN);
        int f  = f0 - 6 + fl;
        int tg = t0 + t;
        float v = 0.f;
        if (f >= 0 && f < NF && tg < NT)
            v = feat[((b * ND + d) * NF + f) * NT + tg];
        s_in[i] = v;
    }
    __syncthreads();

    // Stage B: conv1 + PReLU
    for (int u = tid; u < FC1 * 8; u += 256) {
        int tq  = u & 7;
        int f1i = u >> 3;
        int f1  = f0 - 2 + f1i;
        u64 a2r[CH][2];
        if (f1 >= 0 && f1 < NF) {
            #pragma unroll
            for (int c = 0; c < CH; c++) { a2r[c][0] = s_bd[c]; a2r[c][1] = s_bd[c]; }
            #pragma unroll
            for (int d = 0; d < ND; d++)
                #pragma unroll
                for (int k = 0; k < 9; k++) {
                    const u64* vp = (const u64*)&s_in[(d * FIN + f1i + k) * TT + tq * 4];
                    u64 v0 = vp[0], v1 = vp[1];
                    #pragma unroll
                    for (int c = 0; c < CH; c++) {
                        u64 w = s_w1d[(c * ND + d) * 9 + k];
                        a2r[c][0] = fma2(w, v0, a2r[c][0]);
                        a2r[c][1] = fma2(w, v1, a2r[c][1]);
                    }
                }
            #pragma unroll
            for (int c = 0; c < CH; c++)
                #pragma unroll
                for (int hh = 0; hh < 2; hh++) {
                    float x0, x1;
                    unpack2(a2r[c][hh], x0, x1);
                    x0 = x0 >= 0.f ? x0 : a1 * x0;
                    x1 = x1 >= 0.f ? x1 : a1 * x1;
                    a2r[c][hh] = pack2(x0, x1);
                }
        } else {
            #pragma unroll
            for (int c = 0; c < CH; c++) { a2r[c][0] = 0ull; a2r[c][1] = 0ull; }
        }
        #pragma unroll
        for (int c = 0; c < CH; c++) {
            u64* op = (u64*)&s_c1[(c * FC1 + f1i) * TT + tq * 4];
            op[0] = a2r[c][0]; op[1] = a2r[c][1];
        }
    }
    __syncthreads();

    // Stage C: conv2 + PReLU + layout-converted output
    {
        int tq  = tid & 7;
        int f2i = tid >> 3;
        u64 a2r[CH][2];
        #pragma unroll
        for (int c = 0; c < CH; c++) { a2r[c][0] = s_bd[16 + c]; a2r[c][1] = s_bd[16 + c]; }
        #pragma unroll
        for (int ci = 0; ci < CH; ci++)
            #pragma unroll
            for (int k = 0; k < 5; k++) {
                const u64* vp = (const u64*)&s_c1[(ci * FC1 + f2i + k) * TT + tq * 4];
                u64 v0 = vp[0], v1 = vp[1];
                #pragma unroll
                for (int co = 0; co < CH; co++) {
                    u64 w = s_w2d[(co * CH + ci) * 5 + k];
                    a2r[co][0] = fma2(w, v0, a2r[co][0]);
                    a2r[co][1] = fma2(w, v1, a2r[co][1]);
                }
            }
        float ov[CH][4];
        #pragma unroll
        for (int c = 0; c < CH; c++) {
            unpack2(a2r[c][0], ov[c][0], ov[c][1]);
            unpack2(a2r[c][1], ov[c][2], ov[c][3]);
            #pragma unroll
            for (int tw = 0; tw < 4; tw++) {
                float x = ov[c][tw];
                ov[c][tw] = x >= 0.f ? x : a2 * x;
            }
        }
        int f = f0 + f2i;
        if (f < NF) {
            int seq = b * NF + f;
            size_t base = (size_t)(seq >> 3) * NT * 128 + (seq & 7) * 16;
            #pragma unroll
            for (int tw = 0; tw < 4; tw++) {
                int t = t0 + tq * 4 + tw;
                if (t < NT) {
                    float* o = g_x2 + base + (size_t)t * 128;
                    #pragma unroll
                    for (int c4 = 0; c4 < 4; c4++)
                        *(float4*)(o + c4 * 4) = make_float4(
                            ov[c4 * 4 + 0][tw], ov[c4 * 4 + 1][tw],
                            ov[c4 * 4 + 2][tw], ov[c4 * 4 + 3][tw]);
                }
            }
        }
    }
}

// ---------------------------------------------------------------------------
// Kernel 2: persistent GRU.  962 x 1-warp blocks.  Best-measured version:
// R6 loop + fc software-pipelined by one step (emits prob[t-1] during step t,
// overlapping the fc chains with the main fma2 accumulation).  1073us.
// ---------------------------------------------------------------------------
__global__ __launch_bounds__(32) void gru_kernel(
    const float* __restrict__ h0,
    const float* __restrict__ w_ih, const float* __restrict__ w_hh,
    const float* __restrict__ b_ih, const float* __restrict__ b_hh,
    const float* __restrict__ fc_w, const float* __restrict__ fc_b,
    float* __restrict__ prob, float* __restrict__ hlast)
{
    __shared__ float4 s_whhA[NH][NH];     // [k][j] = (wr,wr,wz,wz)   16KB
    __shared__ u64   s_fcw[NH];           // (fcw,fcw) per k          256B
    __shared__ u64   s_hh[NH][4];         // [k][pair]                1KB
    __shared__ float s_xT[CH][12];        // [c][g] padded            768B

    const int lane = threadIdx.x;
    const int j = lane;

    for (int k = 0; k < NH; k++) {
        float wr = w_hh[j * NH + k];
        float wz = w_hh[(NH + j) * NH + k];
        s_whhA[k][j] = make_float4(wr, wr, wz, wz);
    }
    { float w = fc_w[lane]; s_fcw[lane] = pack2(w, w); }

    const int gw = blockIdx.x;
    const int sbase = gw * GPW;

    u64 wxr[CH], wxz[CH], wxn[CH], whn[NH];
    #pragma unroll
    for (int c = 0; c < CH; c++) {
        float wr = w_ih[j * CH + c];
        float wz = w_ih[(NH + j) * CH + c];
        float wn = w_ih[(2 * NH + j) * CH + c];
        wxr[c] = pack2(wr, wr); wxz[c] = pack2(wz, wz); wxn[c] = pack2(wn, wn);
    }
    #pragma unroll
    for (int k = 0; k < NH; k++) {
        float wn = w_hh[(2 * NH + j) * NH + k];
        whn[k] = pack2(wn, wn);
    }

    const float brf  = b_ih[j] + b_hh[j];
    const float bzf  = b_ih[NH + j] + b_hh[NH + j];
    const float bxnf = b_ih[2 * NH + j];
    const float bhnf = b_hh[2 * NH + j];
    const u64 br2  = pack2(brf, brf);
    const u64 bz2  = pack2(bzf, bzf);
    const u64 bxn2 = pack2(bxnf, bxnf);
    const u64 bhn2 = pack2(bhnf, bhnf);
    const float fcb = fc_b[0];

    float hreg[GPW];
    #pragma unroll
    for (int g = 0; g < GPW; g++) hreg[g] = h0[(sbase + g) * NH + j];
    {
        ulonglong2 v0, v1;
        v0.x = pack2(hreg[0], hreg[1]); v0.y = pack2(hreg[2], hreg[3]);
        v1.x = pack2(hreg[4], hreg[5]); v1.y = pack2(hreg[6], hreg[7]);
        *(ulonglong2*)&s_hh[j][0] = v0;
        *(ulonglong2*)&s_hh[j][2] = v1;
    }

    const int lg = lane >> 2, lc4 = lane & 3;
    const int p = lane & 3;     // fc pair handled (redundantly) by this lane
    const float* xptr = g_x2 + (size_t)gw * NT * 128 + lg * 16 + lc4 * 4;
    float4 xv = *(const float4*)xptr;
    float* sx = &s_xT[0][0];
    __syncwarp();

    for (int t = 0; t < NT; t++) {
        sx[(lc4 * 4 + 0) * 12 + lg] = xv.x;
        sx[(lc4 * 4 + 1) * 12 + lg] = xv.y;
        sx[(lc4 * 4 + 2) * 12 + lg] = xv.z;
        sx[(lc4 * 4 + 3) * 12 + lg] = xv.w;
        __syncwarp();   // publishes x(t) AND the s_hh store from step t-1
        if (t + 1 < NT)
            xv = *(const float4*)(xptr + (size_t)(t + 1) * 128);

        // deferred fc for step t-1 (s_hh holds h_{t-1}); overlaps accumulation
        if (t > 0) {
            u64 f0a = 0ull, f1a = 0ull, f2a = 0ull, f3a = 0ull;
            #pragma unroll
            for (int k8 = 0; k8 < 8; k8++) {
                f0a = fma2(s_fcw[k8],      s_hh[k8][p],      f0a);
                f1a = fma2(s_fcw[8 + k8],  s_hh[8 + k8][p],  f1a);
                f2a = fma2(s_fcw[16 + k8], s_hh[16 + k8][p], f2a);
                f3a = fma2(s_fcw[24 + k8], s_hh[24 + k8][p], f3a);
            }
            u64 facc = add2(add2(f0a, f1a), add2(f2a, f3a));
            float f0v, f1v;
            unpack2(facc, f0v, f1v);
            if (lane < 4) {
                prob[(size_t)(sbase + 2 * p) * NT + (t - 1)]     = sigm(f0v + fcb);
                prob[(size_t)(sbase + 2 * p + 1) * NT + (t - 1)] = sigm(f1v + fcb);
            }
        }

        u64 ar[4], az[4], axn[4], ahn[4];
        #pragma unroll
        for (int q = 0; q < 4; q++) { ar[q] = br2; az[q] = bz2; axn[q] = bxn2; ahn[q] = bhn2; }

        // h @ w_hh^T
        #pragma unroll
        for (int k = 0; k < NH; k++) {
            ulonglong2 wA = *(const ulonglong2*)&s_whhA[k][j];
            ulonglong2 hA = *(const ulonglong2*)&s_hh[k][0];
            ulonglong2 hB = *(const ulonglong2*)&s_hh[k][2];
            ar[0]  = fma2(wA.x,   hA.x, ar[0]);  ar[1]  = fma2(wA.x,   hA.y, ar[1]);
            ar[2]  = fma2(wA.x,   hB.x, ar[2]);  ar[3]  = fma2(wA.x,   hB.y, ar[3]);
            az[0]  = fma2(wA.y,   hA.x, az[0]);  az[1]  = fma2(wA.y,   hA.y, az[1]);
            az[2]  = fma2(wA.y,   hB.x, az[2]);  az[3]  = fma2(wA.y,   hB.y, az[3]);
            ahn[0] = fma2(whn[k], hA.x, ahn[0]); ahn[1] = fma2(whn[k], hA.y, ahn[1]);
            ahn[2] = fma2(whn[k], hB.x, ahn[2]); ahn[3] = fma2(whn[k], hB.y, ahn[3]);
        }
        // x @ w_ih^T
        #pragma unroll
        for (int c = 0; c < CH; c++) {
            const float* r = &s_xT[c][0];
            ulonglong2 xA = *(const ulonglong2*)r;
            ulonglong2 xB = *(const ulonglong2*)(r + 4);
            ar[0]  = fma2(wxr[c], xA.x, ar[0]);  ar[1]  = fma2(wxr[c], xA.y, ar[1]);
            ar[2]  = fma2(wxr[c], xB.x, ar[2]);  ar[3]  = fma2(wxr[c], xB.y, ar[3]);
            az[0]  = fma2(wxz[c], xA.x, az[0]);  az[1]  = fma2(wxz[c], xA.y, az[1]);
            az[2]  = fma2(wxz[c], xB.x, az[2]);  az[3]  = fma2(wxz[c], xB.y, az[3]);
            axn[0] = fma2(wxn[c], xA.x, axn[0]); axn[1] = fma2(wxn[c], xA.y, axn[1]);
            axn[2] = fma2(wxn[c], xB.x, axn[2]); axn[3] = fma2(wxn[c], xB.y, axn[3]);
        }

        float hnew[GPW];
        #pragma unroll
        for (int q = 0; q < 4; q++) {
            float arv0, arv1, azv0, azv1, xn0, xn1, hn0, hn1;
            unpack2(ar[q],  arv0, arv1);
            unpack2(az[q],  azv0, azv1);
            unpack2(axn[q], xn0,  xn1);
            unpack2(ahn[q], hn0,  hn1);
            float r0 = sigm(arv0), r1 = sigm(arv1);
            float z0 = sigm(azv0), z1 = sigm(azv1);
            float n0 = tanh_f(fmaf(r0, hn0, xn0));
            float n1 = tanh_f(fmaf(r1, hn1, xn1));
            hnew[2 * q]     = fmaf(z0, hreg[2 * q]     - n0, n0);
            hnew[2 * q + 1] = fmaf(z1, hreg[2 * q + 1] - n1, n1);
        }

        __syncwarp();   // all lanes' s_hh reads (fc + hh-loop) done
        {
            ulonglong2 v0, v1;
            v0.x = pack2(hnew[0], hnew[1]); v0.y = pack2(hnew[2], hnew[3]);
            v1.x = pack2(hnew[4], hnew[5]); v1.y = pack2(hnew[6], hnew[7]);
            *(ulonglong2*)&s_hh[j][0] = v0;
            *(ulonglong2*)&s_hh[j][2] = v1;
        }
        #pragma unroll
        for (int g = 0; g < GPW; g++) hreg[g] = hnew[g];
    }
    __syncwarp();   // final s_hh store visible

    // epilogue fc for t = NT-1
    {
        u64 f0a = 0ull, f1a = 0ull, f2a = 0ull, f3a = 0ull;
        #pragma unroll
        for (int k8 = 0; k8 < 8; k8++) {
            f0a = fma2(s_fcw[k8],      s_hh[k8][p],      f0a);
            f1a = fma2(s_fcw[8 + k8],  s_hh[8 + k8][p],  f1a);
            f2a = fma2(s_fcw[16 + k8], s_hh[16 + k8][p], f2a);
            f3a = fma2(s_fcw[24 + k8], s_hh[24 + k8][p], f3a);
        }
        u64 facc = add2(add2(f0a, f1a), add2(f2a, f3a));
        float f0v, f1v;
        unpack2(facc, f0v, f1v);
        if (lane < 4) {
            prob[(size_t)(sbase + 2 * p) * NT + (NT - 1)]     = sigm(f0v + fcb);
            prob[(size_t)(sbase + 2 * p + 1) * NT + (NT - 1)] = sigm(f1v + fcb);
        }
    }

    #pragma unroll
    for (int g = 0; g < GPW; g++)
        hlast[(sbase + g) * NH + j] = hreg[g];
}

// ---------------------------------------------------------------------------
extern "C" void kernel_launch(void* const* d_in, const int* in_sizes, int n_in,
                              void* d_out, int out_size)
{
    const float* feat  = (const float*)d_in[0];
    const float* h0    = (const float*)d_in[1];
    const float* w1    = (const float*)d_in[2];
    const float* b1    = (const float*)d_in[3];
    const float* a1    = (const float*)d_in[4];
    const float* w2    = (const float*)d_in[5];
    const float* b2    = (const float*)d_in[6];
    const float* a2    = (const float*)d_in[7];
    const float* w_ih  = (const float*)d_in[8];
    const float* w_hh  = (const float*)d_in[9];
    const float* b_ih  = (const float*)d_in[10];
    const float* b_hh  = (const float*)d_in[11];
    const float* fc_w  = (const float*)d_in[12];
    const float* fc_b  = (const float*)d_in[13];

    float* prob = (float*)d_out;
    float* hlast;
    if (out_size >= PROB_ELEMS + H_ELEMS) {
        hlast = prob + PROB_ELEMS;
    } else {
        void* p = nullptr;
        cudaGetSymbolAddress(&p, g_hdump);
        hlast = (float*)p;
    }

    const int smem_bytes = (W1D + W2D + BD) * 8 + (ND * FIN * TT + CH * FC1 * TT) * 4;
    cudaFuncSetAttribute(conv_kernel, cudaFuncAttributeMaxDynamicSharedMemorySize,
                         smem_bytes);

    dim3 cgrid((NT + TT - 1) / TT, (NF + FT - 1) / FT, NB);   // 16,16,16
    conv_kernel<<<cgrid, 256, smem_bytes>>>(feat, w1, b1, a1, w2, b2, a2);

    gru_kernel<<<NGRP, 32>>>(h0, w_ih, w_hh, b_ih, b_hh, fc_w, fc_b,
                             prob, hlast);
}